// round 1
// baseline (speedup 1.0000x reference)
#include <cuda_runtime.h>
#include <cstdint>
#include <cstddef>

// Problem constants
#define T_STEPS 2048
#define BATCH   16
#define DIM     1024
#define NDIM    64
#define PROJ    256            // 4 * NDIM (k, v, q, a)
#define PSTRIDE 4096           // floats per time step = BATCH * PROJ

// Scratch: projections P[(t*BATCH + b)*256 + c], c = {k:0..63, v:64..127, q:128..191, a:192..255}
__device__ float g_P[(size_t)T_STEPS * BATCH * PROJ];   // 33.5 MB

// ---------------------------------------------------------------------------
// Kernel 1: fused projection GEMM.  P[m][c] = sum_d x[m][d] * W_c[c%64][d]
// M = 32768, K = 1024, N = 256.  Both operands K-major (NT GEMM).
// BM=128, BN=64 (= one W matrix per blockIdx.y), BK=16, 8x8 per thread, 128 thr.
// ---------------------------------------------------------------------------
__global__ __launch_bounds__(128) void proj_gemm(
    const float* __restrict__ x,
    const float* __restrict__ Wk, const float* __restrict__ Wv,
    const float* __restrict__ Wq, const float* __restrict__ Wa)
{
    __shared__ float As[16][128];   // [k][m]
    __shared__ float Bs[16][64];    // [k][c]

    const int tid = threadIdx.x;
    const int m0  = blockIdx.x * 128;
    const int c0  = blockIdx.y * 64;
    const float* W = (blockIdx.y == 0) ? Wk :
                     (blockIdx.y == 1) ? Wv :
                     (blockIdx.y == 2) ? Wq : Wa;

    const int tx = tid & 7;    // c sub-tile (0..7)
    const int ty = tid >> 3;   // m sub-tile (0..15)

    float acc[8][8];
#pragma unroll
    for (int a = 0; a < 8; a++)
#pragma unroll
        for (int b = 0; b < 8; b++) acc[a][b] = 0.0f;

    // global load pointers: each thread loads one full x row-slice (16 floats)
    // and 8 floats of one W row per K-chunk
    const float* xrow = x + (size_t)(m0 + tid) * DIM;
    const int    brow = tid >> 1;
    const int    bcol = (tid & 1) * 8;
    const float* wrow = W + (size_t)brow * DIM + bcol;

    for (int k0 = 0; k0 < DIM; k0 += 16) {
        float4 a0 = *(const float4*)(xrow + k0);
        float4 a1 = *(const float4*)(xrow + k0 + 4);
        float4 a2 = *(const float4*)(xrow + k0 + 8);
        float4 a3 = *(const float4*)(xrow + k0 + 12);
        float4 b0 = *(const float4*)(wrow + k0);
        float4 b1 = *(const float4*)(wrow + k0 + 4);

        __syncthreads();   // previous tile fully consumed
        As[ 0][tid] = a0.x; As[ 1][tid] = a0.y; As[ 2][tid] = a0.z; As[ 3][tid] = a0.w;
        As[ 4][tid] = a1.x; As[ 5][tid] = a1.y; As[ 6][tid] = a1.z; As[ 7][tid] = a1.w;
        As[ 8][tid] = a2.x; As[ 9][tid] = a2.y; As[10][tid] = a2.z; As[11][tid] = a2.w;
        As[12][tid] = a3.x; As[13][tid] = a3.y; As[14][tid] = a3.z; As[15][tid] = a3.w;
        Bs[bcol + 0][brow] = b0.x; Bs[bcol + 1][brow] = b0.y;
        Bs[bcol + 2][brow] = b0.z; Bs[bcol + 3][brow] = b0.w;
        Bs[bcol + 4][brow] = b1.x; Bs[bcol + 5][brow] = b1.y;
        Bs[bcol + 6][brow] = b1.z; Bs[bcol + 7][brow] = b1.w;
        __syncthreads();

#pragma unroll
        for (int k = 0; k < 16; k++) {
            float af[8], bf[8];
            *(float4*)(af)     = *(const float4*)&As[k][ty * 8];
            *(float4*)(af + 4) = *(const float4*)&As[k][ty * 8 + 4];
            *(float4*)(bf)     = *(const float4*)&Bs[k][tx * 8];
            *(float4*)(bf + 4) = *(const float4*)&Bs[k][tx * 8 + 4];
#pragma unroll
            for (int im = 0; im < 8; im++)
#pragma unroll
                for (int ic = 0; ic < 8; ic++)
                    acc[im][ic] = fmaf(af[im], bf[ic], acc[im][ic]);
        }
    }

#pragma unroll
    for (int im = 0; im < 8; im++) {
        float* dst = g_P + (size_t)(m0 + ty * 8 + im) * PROJ + c0 + tx * 8;
        *(float4*)(dst)     = make_float4(acc[im][0], acc[im][1], acc[im][2], acc[im][3]);
        *(float4*)(dst + 4) = make_float4(acc[im][4], acc[im][5], acc[im][6], acc[im][7]);
    }
}

// ---------------------------------------------------------------------------
// Kernel 2: sequential scan.  B*N = 1024 independent row-recurrences.
// 8 threads per row (8 state columns each), 128-thread CTA = 16 rows,
// grid = 64 CTAs (4 row-blocks x 16 batches).
// Software pipeline: distance-2 register double buffering + L2 prefetch.
// ---------------------------------------------------------------------------
__device__ __forceinline__ float fast_sigmoid(float z)
{
    float e = __expf(-z);
    return __fdividef(1.0f, 1.0f + e);
}

__device__ __forceinline__ void load_step(const float* __restrict__ Pb, int t,
                                          int i, int lane8,
                                          float (&k)[8], float (&q)[8],
                                          float& v, float& a)
{
    const float* p = Pb + (size_t)t * PSTRIDE;
    float4 x0 = *(const float4*)(p + lane8 * 8);
    float4 x1 = *(const float4*)(p + lane8 * 8 + 4);
    float4 y0 = *(const float4*)(p + 128 + lane8 * 8);
    float4 y1 = *(const float4*)(p + 128 + lane8 * 8 + 4);
    k[0] = x0.x; k[1] = x0.y; k[2] = x0.z; k[3] = x0.w;
    k[4] = x1.x; k[5] = x1.y; k[6] = x1.z; k[7] = x1.w;
    q[0] = y0.x; q[1] = y0.y; q[2] = y0.z; q[3] = y0.w;
    q[4] = y1.x; q[5] = y1.y; q[6] = y1.z; q[7] = y1.w;
    v = p[64 + i];
    a = p[192 + i];
}

__device__ __forceinline__ void do_step(int t, int b, int i, int lane8, int tid,
                                        float di, float bi, float (&S)[8],
                                        float (&k)[8], float (&q)[8],
                                        float& v, float& a,
                                        const float* __restrict__ Pb,
                                        float* __restrict__ out)
{
    // L2 prefetch ~8 steps ahead (hides DRAM first-touch; warp covers 1KB block)
    {
        int tp = t + 8; if (tp > T_STEPS - 1) tp = T_STEPS - 1;
        const float* pf = Pb + (size_t)tp * PSTRIDE + (tid & 31) * 8;
        asm volatile("prefetch.global.L2 [%0];" :: "l"(pf));
    }

    // retrieved_i = sum_j S[i][j] * k[j]
    float r0 = 0.0f, r1 = 0.0f;
#pragma unroll
    for (int j = 0; j < 8; j += 2) {
        r0 = fmaf(S[j],     k[j],     r0);
        r1 = fmaf(S[j + 1], k[j + 1], r1);
    }
    float rk = r0 + r1;
    rk += __shfl_xor_sync(0xffffffffu, rk, 1);
    rk += __shfl_xor_sync(0xffffffffu, rk, 2);
    rk += __shfl_xor_sync(0xffffffffu, rk, 4);

    float z     = fmaf(di, rk, a) + bi;
    float alpha = fast_sigmoid(z);
    float c     = (1.0f - alpha) * v;

    // S = alpha*S + (1-alpha) * v * k^T
#pragma unroll
    for (int j = 0; j < 8; j++) S[j] = fmaf(alpha, S[j], c * k[j]);

    // out_i = S[i] . q
    float p0 = 0.0f, p1 = 0.0f;
#pragma unroll
    for (int j = 0; j < 8; j += 2) {
        p0 = fmaf(S[j],     q[j],     p0);
        p1 = fmaf(S[j + 1], q[j + 1], p1);
    }
    float rq = p0 + p1;
    rq += __shfl_xor_sync(0xffffffffu, rq, 1);
    rq += __shfl_xor_sync(0xffffffffu, rq, 2);
    rq += __shfl_xor_sync(0xffffffffu, rq, 4);

    // Refill this buffer with step t+2 (last use of k/q/v/a is above)
    {
        int t2 = t + 2; if (t2 > T_STEPS - 1) t2 = T_STEPS - 1;
        load_step(Pb, t2, i, lane8, k, q, v, a);
    }

    // out = rq * silu(rq) = rq^2 * sigmoid(rq)
    float res = rq * rq * fast_sigmoid(rq);
    if (lane8 == 0)
        out[((size_t)t * BATCH + b) * NDIM + i] = res;
}

__global__ __launch_bounds__(128) void scan_kernel(
    const float* __restrict__ S0,
    const float* __restrict__ dA, const float* __restrict__ bA,
    float* __restrict__ out, float* __restrict__ Sout, int writeS)
{
    const int tid   = threadIdx.x;
    const int b     = blockIdx.x >> 2;       // batch
    const int rb    = blockIdx.x & 3;        // row block (16 rows each)
    const int rl    = tid >> 3;              // local row 0..15
    const int lane8 = tid & 7;               // column-slice within row
    const int i     = rb * 16 + rl;          // global row 0..63

    const float* Pb = g_P + b * PROJ;

    float S[8];
    {
        const float* sp = S0 + ((size_t)b * NDIM + i) * NDIM + lane8 * 8;
        float4 s0 = *(const float4*)sp;
        float4 s1 = *(const float4*)(sp + 4);
        S[0] = s0.x; S[1] = s0.y; S[2] = s0.z; S[3] = s0.w;
        S[4] = s1.x; S[5] = s1.y; S[6] = s1.z; S[7] = s1.w;
    }
    const float di = dA[i];
    const float bi = bA[i];

    float kA[8], qA[8], vA, aA;
    float kB[8], qB[8], vB, aB;
    load_step(Pb, 0, i, lane8, kA, qA, vA, aA);
    load_step(Pb, 1, i, lane8, kB, qB, vB, aB);

#pragma unroll 1
    for (int t = 0; t < T_STEPS; t += 2) {
        do_step(t,     b, i, lane8, tid, di, bi, S, kA, qA, vA, aA, Pb, out);
        do_step(t + 1, b, i, lane8, tid, di, bi, S, kB, qB, vB, aB, Pb, out);
    }

    if (writeS) {
        float* sp = Sout + ((size_t)b * NDIM + i) * NDIM + lane8 * 8;
        *(float4*)(sp)     = make_float4(S[0], S[1], S[2], S[3]);
        *(float4*)(sp + 4) = make_float4(S[4], S[5], S[6], S[7]);
    }
}

// ---------------------------------------------------------------------------
extern "C" void kernel_launch(void* const* d_in, const int* in_sizes, int n_in,
                              void* d_out, int out_size)
{
    const float* x  = (const float*)d_in[0];
    const float* S0 = (const float*)d_in[1];
    const float* Wk = (const float*)d_in[2];
    const float* Wv = (const float*)d_in[3];
    const float* Wq = (const float*)d_in[4];
    const float* Wa = (const float*)d_in[5];
    const float* dA = (const float*)d_in[6];
    const float* bA = (const float*)d_in[7];

    float* out = (float*)d_out;
    const size_t out_elems = (size_t)T_STEPS * BATCH * NDIM;          // 2,097,152
    const size_t s_elems   = (size_t)BATCH * NDIM * NDIM;             //    65,536
    int writeS = ((size_t)out_size >= out_elems + s_elems) ? 1 : 0;
    float* Sout = out + out_elems;

    dim3 grid_g(T_STEPS * BATCH / 128, 4);   // (256, 4)
    proj_gemm<<<grid_g, 128>>>(x, Wk, Wv, Wq, Wa);

    scan_kernel<<<64, 128>>>(S0, dA, bA, out, Sout, writeS);
}

// round 3
// speedup vs baseline: 1.1614x; 1.1614x over previous
#include <cuda_runtime.h>
#include <cstdint>
#include <cstddef>

// Problem constants
#define T_STEPS 2048
#define BATCH   16
#define DIM     1024
#define NDIM    64
#define PROJ    256            // 4 * NDIM (k, v, q, a)
#define PSTRIDE 4096           // floats per time step = BATCH * PROJ

// Scratch: projections P[(t*BATCH + b)*256 + c], c = {k:0..63, v:64..127, q:128..191, a:192..255}
__device__ float g_P[(size_t)T_STEPS * BATCH * PROJ];   // 33.5 MB

// ---------------------------------------------------------------------------
// Kernel 1: fused projection GEMM (unchanged — at the fp32 FFMA roofline).
// ---------------------------------------------------------------------------
__global__ __launch_bounds__(128) void proj_gemm(
    const float* __restrict__ x,
    const float* __restrict__ Wk, const float* __restrict__ Wv,
    const float* __restrict__ Wq, const float* __restrict__ Wa)
{
    __shared__ float As[16][128];   // [k][m]
    __shared__ float Bs[16][64];    // [k][c]

    const int tid = threadIdx.x;
    const int m0  = blockIdx.x * 128;
    const int c0  = blockIdx.y * 64;
    const float* W = (blockIdx.y == 0) ? Wk :
                     (blockIdx.y == 1) ? Wv :
                     (blockIdx.y == 2) ? Wq : Wa;

    const int tx = tid & 7;    // c sub-tile (0..7)
    const int ty = tid >> 3;   // m sub-tile (0..15)

    float acc[8][8];
#pragma unroll
    for (int a = 0; a < 8; a++)
#pragma unroll
        for (int b = 0; b < 8; b++) acc[a][b] = 0.0f;

    const float* xrow = x + (size_t)(m0 + tid) * DIM;
    const int    brow = tid >> 1;
    const int    bcol = (tid & 1) * 8;
    const float* wrow = W + (size_t)brow * DIM + bcol;

    for (int k0 = 0; k0 < DIM; k0 += 16) {
        float4 a0 = *(const float4*)(xrow + k0);
        float4 a1 = *(const float4*)(xrow + k0 + 4);
        float4 a2 = *(const float4*)(xrow + k0 + 8);
        float4 a3 = *(const float4*)(xrow + k0 + 12);
        float4 b0 = *(const float4*)(wrow + k0);
        float4 b1 = *(const float4*)(wrow + k0 + 4);

        __syncthreads();
        As[ 0][tid] = a0.x; As[ 1][tid] = a0.y; As[ 2][tid] = a0.z; As[ 3][tid] = a0.w;
        As[ 4][tid] = a1.x; As[ 5][tid] = a1.y; As[ 6][tid] = a1.z; As[ 7][tid] = a1.w;
        As[ 8][tid] = a2.x; As[ 9][tid] = a2.y; As[10][tid] = a2.z; As[11][tid] = a2.w;
        As[12][tid] = a3.x; As[13][tid] = a3.y; As[14][tid] = a3.z; As[15][tid] = a3.w;
        Bs[bcol + 0][brow] = b0.x; Bs[bcol + 1][brow] = b0.y;
        Bs[bcol + 2][brow] = b0.z; Bs[bcol + 3][brow] = b0.w;
        Bs[bcol + 4][brow] = b1.x; Bs[bcol + 5][brow] = b1.y;
        Bs[bcol + 6][brow] = b1.z; Bs[bcol + 7][brow] = b1.w;
        __syncthreads();

#pragma unroll
        for (int k = 0; k < 16; k++) {
            float af[8], bf[8];
            *(float4*)(af)     = *(const float4*)&As[k][ty * 8];
            *(float4*)(af + 4) = *(const float4*)&As[k][ty * 8 + 4];
            *(float4*)(bf)     = *(const float4*)&Bs[k][tx * 8];
            *(float4*)(bf + 4) = *(const float4*)&Bs[k][tx * 8 + 4];
#pragma unroll
            for (int im = 0; im < 8; im++)
#pragma unroll
                for (int ic = 0; ic < 8; ic++)
                    acc[im][ic] = fmaf(af[im], bf[ic], acc[im][ic]);
        }
    }

#pragma unroll
    for (int im = 0; im < 8; im++) {
        float* dst = g_P + (size_t)(m0 + ty * 8 + im) * PROJ + c0 + tx * 8;
        *(float4*)(dst)     = make_float4(acc[im][0], acc[im][1], acc[im][2], acc[im][3]);
        *(float4*)(dst + 4) = make_float4(acc[im][4], acc[im][5], acc[im][6], acc[im][7]);
    }
}

// ---------------------------------------------------------------------------
// Kernel 2: sequential scan with one-step algebraic lookahead.
//   retrieved(t) = a(t-1)*u(t) + (1-a(t-1))*v(t-1)*w(t)
//     u(t) = S(t-2).k(t),  w(t) = k(t-1).k(t)      [reductions off-chain]
//   out(t) = a(t)*p(t) + (1-a(t))*v(t)*(k(t).q(t)),  p(t) = S(t-1).q(t)
// Critical chain per step: 2 FFMA + EX2 + FADD + RCP  (~48 cy)
// 8 lanes per row, 16 rows per 128-thr CTA, 64 CTAs.  Ring-of-4 reg buffers.
// ---------------------------------------------------------------------------
#define LOG2E 1.44269504f

__device__ __forceinline__ float sigmoid_neg_l2(float z2)  // z2 = -log2(e)*z -> sigmoid(z)
{
    float e;
    asm("ex2.approx.f32 %0, %1;" : "=f"(e) : "f"(z2));
    float den = 1.0f + e;
    float r;
    asm("rcp.approx.f32 %0, %1;" : "=f"(r) : "f"(den));
    return r;
}

__device__ __forceinline__ void load_step(const float* __restrict__ Pb, int t,
                                          int i, int lane8,
                                          float (&k)[8], float (&q)[8],
                                          float& v, float& a)
{
    const float* p = Pb + (size_t)t * PSTRIDE;
    float4 x0 = *(const float4*)(p + lane8 * 8);
    float4 x1 = *(const float4*)(p + lane8 * 8 + 4);
    float4 y0 = *(const float4*)(p + 128 + lane8 * 8);
    float4 y1 = *(const float4*)(p + 128 + lane8 * 8 + 4);
    k[0] = x0.x; k[1] = x0.y; k[2] = x0.z; k[3] = x0.w;
    k[4] = x1.x; k[5] = x1.y; k[6] = x1.z; k[7] = x1.w;
    q[0] = y0.x; q[1] = y0.y; q[2] = y0.z; q[3] = y0.w;
    q[4] = y1.x; q[5] = y1.y; q[6] = y1.z; q[7] = y1.w;
    v = p[64 + i];
    a = p[192 + i];
}

__global__ __launch_bounds__(128, 1) void scan_kernel(
    const float* __restrict__ S0,
    const float* __restrict__ dA, const float* __restrict__ bA,
    float* __restrict__ out, float* __restrict__ Sout, int writeS)
{
    const int tid   = threadIdx.x;
    const int b     = blockIdx.x >> 2;       // batch
    const int rb    = blockIdx.x & 3;        // row block (16 rows each)
    const int rl    = tid >> 3;              // local row 0..15
    const int lane8 = tid & 7;               // column-slice within row
    const int i     = rb * 16 + rl;          // global row 0..63

    const float* Pb = g_P + b * PROJ;

    float S[8];
    {
        const float* sp = S0 + ((size_t)b * NDIM + i) * NDIM + lane8 * 8;
        float4 s0 = *(const float4*)sp;
        float4 s1 = *(const float4*)(sp + 4);
        S[0] = s0.x; S[1] = s0.y; S[2] = s0.z; S[3] = s0.w;
        S[4] = s1.x; S[5] = s1.y; S[6] = s1.z; S[7] = s1.w;
    }
    const float c1 = -LOG2E * dA[i];
    const float bi = bA[i];

    // ring-of-4 register buffers (distance-4 load pipeline)
    float kb[4][8], qb[4][8], vb[4], ab[4];
#pragma unroll
    for (int s = 0; s < 4; s++)
        load_step(Pb, s, i, lane8, kb[s], qb[s], vb[s], ab[s]);

    // Prologue: virtual step -1 with alpha=1, v=0  =>  retrieved(0) = S0.k(0)
    float u0 = 0.0f;
#pragma unroll
    for (int j = 0; j < 8; j++) u0 = fmaf(S[j], kb[0][j], u0);
#pragma unroll
    for (int m = 1; m < 8; m <<= 1) u0 += __shfl_xor_sync(0xffffffffu, u0, m);

    float alpha_prev = 1.0f;
    float base  = 0.0f;
    float delta = u0;
    float c0    = -LOG2E * (ab[0] + bi);

    float* orow = out + (size_t)b * NDIM + i;

#pragma unroll 1
    for (int t = 0; t < T_STEPS; t += 4) {
#pragma unroll
        for (int c = 0; c < 4; c++) {
            const int tt = t + c;
            const int cn = (c + 1) & 3;

            // ---- off-chain reductions (use S(t-1), loaded k/q) ----
            float un = 0.0f, pq = 0.0f, wn = 0.0f, wq = 0.0f;
#pragma unroll
            for (int j = 0; j < 8; j++) {
                un = fmaf(S[j],        kb[cn][j], un);   // S(t-1).k(t+1)
                pq = fmaf(S[j],        qb[c][j],  pq);   // S(t-1).q(t)
                wn = fmaf(kb[c][j],    kb[cn][j], wn);   // k(t).k(t+1)
                wq = fmaf(kb[c][j],    qb[c][j],  wq);   // k(t).q(t)
            }
#pragma unroll
            for (int m = 1; m < 8; m <<= 1) {
                un += __shfl_xor_sync(0xffffffffu, un, m);
                pq += __shfl_xor_sync(0xffffffffu, pq, m);
                wn += __shfl_xor_sync(0xffffffffu, wn, m);
                wq += __shfl_xor_sync(0xffffffffu, wq, m);
            }

            // ---- critical chain: alpha(t) from alpha(t-1) ----
            float retrieved = fmaf(alpha_prev, delta, base);
            float z2        = fmaf(c1, retrieved, c0);
            float alpha     = sigmoid_neg_l2(z2);

            // ---- state update: S(t) = a*S(t-1) + (1-a)*v*k(t) ----
            const float v  = vb[c];
            const float cc = (1.0f - alpha) * v;
#pragma unroll
            for (int j = 0; j < 8; j++)
                S[j] = fmaf(alpha, S[j], cc * kb[c][j]);

            // ---- output: out = o^2 * sigmoid(o),  o = a*p + (1-a)*v*(k.q) ----
            float vwq = v * wq;
            float o   = fmaf(alpha, pq - vwq, vwq);
            float res = o * o * sigmoid_neg_l2(-LOG2E * o);
            if (lane8 == 0)
                orow[(size_t)tt * (BATCH * NDIM)] = res;

            // ---- carries for step t+1 ----
            base       = v * wn;          // v(t)*w(t+1)
            delta      = un - base;       // u(t+1) - v(t)*w(t+1)
            alpha_prev = alpha;
            c0         = -LOG2E * (ab[cn] + bi);

            // ---- refill slot c with step tt+4; prefetch L2 further out ----
            {
                int t4 = tt + 4;  if (t4 > T_STEPS - 1) t4 = T_STEPS - 1;
                load_step(Pb, t4, i, lane8, kb[c], qb[c], vb[c], ab[c]);
                int tp = tt + 16; if (tp > T_STEPS - 1) tp = T_STEPS - 1;
                const float* pf = Pb + (size_t)tp * PSTRIDE + (tid & 31) * 8;
                asm volatile("prefetch.global.L2 [%0];" :: "l"(pf));
            }
        }
    }

    if (writeS) {
        float* sp = Sout + ((size_t)b * NDIM + i) * NDIM + lane8 * 8;
        *(float4*)(sp)     = make_float4(S[0], S[1], S[2], S[3]);
        *(float4*)(sp + 4) = make_float4(S[4], S[5], S[6], S[7]);
    }
}

// ---------------------------------------------------------------------------
extern "C" void kernel_launch(void* const* d_in, const int* in_sizes, int n_in,
                              void* d_out, int out_size)
{
    const float* x  = (const float*)d_in[0];
    const float* S0 = (const float*)d_in[1];
    const float* Wk = (const float*)d_in[2];
    const float* Wv = (const float*)d_in[3];
    const float* Wq = (const float*)d_in[4];
    const float* Wa = (const float*)d_in[5];
    const float* dA = (const float*)d_in[6];
    const float* bA = (const float*)d_in[7];

    float* out = (float*)d_out;
    const size_t out_elems = (size_t)T_STEPS * BATCH * NDIM;          // 2,097,152
    const size_t s_elems   = (size_t)BATCH * NDIM * NDIM;             //    65,536
    int writeS = ((size_t)out_size >= out_elems + s_elems) ? 1 : 0;
    float* Sout = out + out_elems;

    dim3 grid_g(T_STEPS * BATCH / 128, 4);   // (256, 4)
    proj_gemm<<<grid_g, 128>>>(x, Wk, Wv, Wq, Wa);

    scan_kernel<<<64, 128>>>(S0, dA, bA, out, Sout, writeS);
}